// round 7
// baseline (speedup 1.0000x reference)
#include <cuda_runtime.h>
#include <cuda_bf16.h>
#include <math.h>
#include <stdint.h>

#define NN 1024
#define BB 128
#define NT 256            // 2*BB interleaved sin/cos columns
#define DT 0.1f
#define STEPS 10

#define TM 64             // CTA tile M (i)
#define TN 32             // CTA tile N (interleaved cols) = 16 b's
#define BK 64             // K chunk
#define NCH (NN / BK)     // 16 chunks

// ---------------- scratch (__device__ globals; no cudaMalloc) --------------
__device__ __nv_bfloat16 g_Kb[NN * NN];        // K in bf16, row-major [i][j]
__device__ __nv_bfloat16 g_scB[2][NT * NN];    // ping-pong B operand: [n][j]
__device__ float         g_theta[NN * BB];     // wrapped theta, [i][b]

// ---------------- PTX helpers ----------------------------------------------
__device__ __forceinline__ uint32_t smem_u32(const void* p) {
    uint32_t a;
    asm("{ .reg .u64 t; cvta.to.shared.u64 t, %1; cvt.u32.u64 %0, t; }" : "=r"(a) : "l"(p));
    return a;
}
__device__ __forceinline__ void cp16(uint32_t dst, const void* src) {
    asm volatile("cp.async.cg.shared.global [%0], [%1], 16;" :: "r"(dst), "l"(src));
}
#define CP_COMMIT() asm volatile("cp.async.commit_group;" ::: "memory")
#define CP_WAIT0()  asm volatile("cp.async.wait_group 0;" ::: "memory")

__device__ __forceinline__ void ldm4(uint32_t& r0, uint32_t& r1, uint32_t& r2, uint32_t& r3,
                                     uint32_t addr) {
    asm volatile("ldmatrix.sync.aligned.m8n8.x4.shared.b16 {%0,%1,%2,%3}, [%4];"
                 : "=r"(r0), "=r"(r1), "=r"(r2), "=r"(r3) : "r"(addr));
}
__device__ __forceinline__ void mma_bf16(float* d, const uint32_t* a, uint32_t b0, uint32_t b1) {
    asm volatile(
        "mma.sync.aligned.m16n8k16.row.col.f32.bf16.bf16.f32 "
        "{%0,%1,%2,%3}, {%4,%5,%6,%7}, {%8,%9}, {%0,%1,%2,%3};"
        : "+f"(d[0]), "+f"(d[1]), "+f"(d[2]), "+f"(d[3])
        : "r"(a[0]), "r"(a[1]), "r"(a[2]), "r"(a[3]), "r"(b0), "r"(b1));
}

// ---------------------------------------------------------------------------
// init 1: K (f32) -> bf16
// ---------------------------------------------------------------------------
__global__ void convK_kernel(const float* __restrict__ Kmat) {
    int g = blockIdx.x * blockDim.x + threadIdx.x;
    if (g >= NN * NN / 4) return;
    float4 v = reinterpret_cast<const float4*>(Kmat)[g];
    __nv_bfloat162* d = reinterpret_cast<__nv_bfloat162*>(g_Kb) + g * 2;
    d[0] = __floats2bfloat162_rn(v.x, v.y);
    d[1] = __floats2bfloat162_rn(v.z, v.w);
}

// ---------------------------------------------------------------------------
// init 2: theta_init [b][i] -> g_theta [i][b]; B operand rows 2b / 2b+1
// ---------------------------------------------------------------------------
__global__ void init_theta_kernel(const float* __restrict__ theta_init) {
    int g = blockIdx.x * blockDim.x + threadIdx.x;     // g = b*NN + i
    if (g >= BB * NN) return;
    int b = g >> 10, i = g & (NN - 1);
    float t = theta_init[g];
    float s, c;
    sincosf(t, &s, &c);
    g_theta[i * BB + b] = t;
    g_scB[0][(2 * b) * NN + i]     = __float2bfloat16(s);
    g_scB[0][(2 * b + 1) * NN + i] = __float2bfloat16(c);
}

// ---------------------------------------------------------------------------
// fused step: D[i,n] = sum_j Kb[i,j] * scB[cur][n,j]  (bf16 HMMA, f32 acc)
// then per (i,b): coupling = cos_i*S - sin_i*C; Euler; wrap; emit scB[nxt].
// grid (16,8)=128 CTAs, 256 thr (8 warps: 4 m-warps x 2 n-warps, m16 x n16).
// ---------------------------------------------------------------------------
__global__ __launch_bounds__(256) void step_kernel(const float* __restrict__ omega,
                                                   const float* __restrict__ Kg,
                                                   int cur, int nxt) {
    __shared__ __nv_bfloat16 sA[2][TM * BK];   // swizzled, 8KB per buf
    __shared__ __nv_bfloat16 sB[2][TN * BK];   // swizzled, 4KB per buf

    const int t = threadIdx.x;
    const int lane = t & 31;
    const int wid = t >> 5;
    const int wm = wid & 3;                    // m-warp 0..3
    const int wn = wid >> 2;                   // n-warp 0..1
    const int i0 = blockIdx.x * TM;
    const int n0 = blockIdx.y * TN;

    const uint32_t sAu = smem_u32(sA);
    const uint32_t sBu = smem_u32(sB);
    const __nv_bfloat16* __restrict__ Bsrc = g_scB[cur];

    // ---- per-thread load indices (A: 2 chunks, B: 1 chunk of 16B) ----
    // A: e in [0,512): row r=e>>3 (0..63), chunk c=e&7. swizzle: c ^= (r&7)
    int ea0 = t, ea1 = t + 256;
    int ar0 = ea0 >> 3, ac0 = ea0 & 7;
    int ar1 = ea1 >> 3, ac1 = ea1 & 7;
    uint32_t adst0 = sAu + (uint32_t)(ar0 * 128 + ((ac0 ^ (ar0 & 7)) << 4));
    uint32_t adst1 = sAu + (uint32_t)(ar1 * 128 + ((ac1 ^ (ar1 & 7)) << 4));
    int br = t >> 3, bc = t & 7;               // B rows 0..31
    uint32_t bdst = sBu + (uint32_t)(br * 128 + ((bc ^ (br & 7)) << 4));

    const __nv_bfloat16* asrc0 = &g_Kb[(size_t)(i0 + ar0) * NN + ac0 * 8];
    const __nv_bfloat16* asrc1 = &g_Kb[(size_t)(i0 + ar1) * NN + ac1 * 8];
    const __nv_bfloat16* bsrc  = &Bsrc[(size_t)(n0 + br) * NN + bc * 8];

    // ---- ldmatrix lane addressing (row part fixed per lane) ----
    int sub = lane >> 3, lr = lane & 7;
    int arow = wm * 16 + ((sub & 1) << 3) + lr;          // A: m0-7/m8-15 pairs
    int acsel = sub >> 1;                                 // k half
    uint32_t aBase = sAu + (uint32_t)(arow * 128);
    int axor = (arow & 7);

    int brow = wn * 16 + ((sub >> 1) << 3) + lr;          // B: n0-7/n8-15
    int bcsel = sub & 1;                                  // k half
    uint32_t bBase = sBu + (uint32_t)(brow * 128);
    int bxor = (brow & 7);

    float acc0[4] = {0.f, 0.f, 0.f, 0.f};    // n8 block 0
    float acc1[4] = {0.f, 0.f, 0.f, 0.f};    // n8 block 1

    // ---- prologue: load chunk 0 into buf 0 ----
    cp16(adst0, asrc0);
    cp16(adst1, asrc1);
    cp16(bdst, bsrc);
    CP_COMMIT();

    for (int k = 0; k < NCH; k++) {
        CP_WAIT0();
        __syncthreads();
        int buf = k & 1;
        if (k + 1 < NCH) {
            int nb = (k + 1) & 1;
            size_t koff = (size_t)(k + 1) * BK;
            cp16(adst0 + nb * (TM * BK * 2), asrc0 + koff);
            cp16(adst1 + nb * (TM * BK * 2), asrc1 + koff);
            cp16(bdst + nb * (TN * BK * 2), bsrc + koff);
            CP_COMMIT();
        }
        uint32_t aB = aBase + (uint32_t)(buf * (TM * BK * 2));
        uint32_t bB = bBase + (uint32_t)(buf * (TN * BK * 2));
        #pragma unroll
        for (int ks = 0; ks < 4; ks++) {
            uint32_t a[4], b[4];
            int ach = ks * 2 + acsel;
            int bch = ks * 2 + bcsel;
            ldm4(a[0], a[1], a[2], a[3], aB + (uint32_t)((ach ^ axor) << 4));
            ldm4(b[0], b[1], b[2], b[3], bB + (uint32_t)((bch ^ bxor) << 4));
            mma_bf16(acc0, a, b[0], b[1]);
            mma_bf16(acc1, a, b[2], b[3]);
        }
        __syncthreads();
    }

    // ---- fused epilogue ----
    const float kgn = Kg[0] * (1.0f / (float)NN);
    const int tq = lane >> 2;        // fragment row within m8
    const int tr = lane & 3;         // fragment col pair
    __nv_bfloat16* __restrict__ Bn = g_scB[nxt];

    #pragma unroll
    for (int nb = 0; nb < 2; nb++) {
        const float* acc = nb ? acc1 : acc0;
        int n_even = n0 + wn * 16 + nb * 8 + tr * 2;   // even column = sin
        int b = n_even >> 1;
        #pragma unroll
        for (int half = 0; half < 2; half++) {
            int i = i0 + wm * 16 + half * 8 + tq;
            float S = acc[half * 2 + 0];
            float C = acc[half * 2 + 1];
            int idx = i * BB + b;
            float th = g_theta[idx];
            float si, ci;
            sincosf(th, &si, &ci);
            float coup = ci * S - si * C;
            float tn = th + DT * (omega[i] + kgn * coup);
            float s, c;
            sincosf(tn, &s, &c);
            g_theta[idx] = atan2f(s, c);               // wrap like reference
            Bn[(size_t)(2 * b) * NN + i]     = __float2bfloat16(s);
            Bn[(size_t)(2 * b + 1) * NN + i] = __float2bfloat16(c);
        }
    }
}

// ---------------------------------------------------------------------------
// finalize: theta -> out[0:B*N] (transposed), coherence -> out[B*N : +B]
// ---------------------------------------------------------------------------
__global__ void finalize_kernel(float* __restrict__ out) {
    int b = blockIdx.x;
    int t = threadIdx.x;
    __shared__ float rc[256], rs[256];

    float sumc = 0.f, sums = 0.f;
    for (int i = t; i < NN; i += 256) {
        float th = g_theta[i * BB + b];
        out[b * NN + i] = th;
        float s, c;
        sincosf(th, &s, &c);
        sums += s;
        sumc += c;
    }
    rc[t] = sumc; rs[t] = sums;
    __syncthreads();
    for (int off = 128; off > 0; off >>= 1) {
        if (t < off) { rc[t] += rc[t + off]; rs[t] += rs[t + off]; }
        __syncthreads();
    }
    if (t == 0) {
        float cm = rc[0] * (1.0f / (float)NN);
        float sm = rs[0] * (1.0f / (float)NN);
        out[BB * NN + b] = sqrtf(cm * cm + sm * sm);
    }
}

// ---------------------------------------------------------------------------
extern "C" void kernel_launch(void* const* d_in, const int* in_sizes, int n_in,
                              void* d_out, int out_size) {
    const float* theta_init = (const float*)d_in[0];
    const float* Kmat       = (const float*)d_in[1];
    const float* omega      = (const float*)d_in[2];
    const float* Kg         = (const float*)d_in[3];
    float* out = (float*)d_out;

    convK_kernel<<<NN * NN / 4 / 256, 256>>>(Kmat);
    init_theta_kernel<<<BB * NN / 256, 256>>>(theta_init);

    dim3 ggrid(NN / TM, NT / TN);   // (16, 8) = 128 CTAs
    for (int s = 0; s < STEPS; s++) {
        step_kernel<<<ggrid, 256>>>(omega, Kg, s & 1, (s + 1) & 1);
    }
    finalize_kernel<<<BB, 256>>>(out);
}

// round 8
// speedup vs baseline: 1.7378x; 1.7378x over previous
#include <cuda_runtime.h>
#include <cuda_bf16.h>
#include <math.h>
#include <stdint.h>

#define NN 1024
#define BB 128
#define NT 256
#define DT 0.1f
#define STEPS 10

#define TM 64
#define TN 32
#define BK 64
#define NCH 16            // K chunks of 64
#define GRID 128          // 16 i-tiles x 8 n-tiles, all co-resident (<=148 SMs)
#define THREADS 256

#define SA_BYTES (NCH * TM * BK * 2)   /* 128 KB: whole A tile, resident */
#define SB_STAGE (TN * BK * 2)         /* 4 KB per pipeline stage */
#define SB_BYTES (4 * SB_STAGE)        /* 4 stages */
#define SM_TOTAL (SA_BYTES + SB_BYTES + 512)

// ---------------- device scratch (no cudaMalloc) ----------------------------
__device__ __nv_bfloat16 g_scB[2][NT * NN];   // ping-pong B operand [n][j]
__device__ float g_redS[BB];
__device__ float g_redC[BB];
__device__ unsigned g_cnt = 0;
__device__ unsigned g_gen = 0;

// ---------------- PTX helpers ----------------------------------------------
__device__ __forceinline__ uint32_t smem_u32(const void* p) {
    uint32_t a;
    asm("{ .reg .u64 t; cvta.to.shared.u64 t, %1; cvt.u32.u64 %0, t; }" : "=r"(a) : "l"(p));
    return a;
}
__device__ __forceinline__ void cp16(uint32_t dst, const void* src) {
    asm volatile("cp.async.cg.shared.global [%0], [%1], 16;" :: "r"(dst), "l"(src));
}
#define CP_COMMIT() asm volatile("cp.async.commit_group;" ::: "memory")
#define CP_WAIT2()  asm volatile("cp.async.wait_group 2;" ::: "memory")

__device__ __forceinline__ void ldm4(uint32_t& r0, uint32_t& r1, uint32_t& r2, uint32_t& r3,
                                     uint32_t addr) {
    asm volatile("ldmatrix.sync.aligned.m8n8.x4.shared.b16 {%0,%1,%2,%3}, [%4];"
                 : "=r"(r0), "=r"(r1), "=r"(r2), "=r"(r3) : "r"(addr));
}
__device__ __forceinline__ void mma_bf16(float* d, const uint32_t* a, uint32_t b0, uint32_t b1) {
    asm volatile(
        "mma.sync.aligned.m16n8k16.row.col.f32.bf16.bf16.f32 "
        "{%0,%1,%2,%3}, {%4,%5,%6,%7}, {%8,%9}, {%0,%1,%2,%3};"
        : "+f"(d[0]), "+f"(d[1]), "+f"(d[2]), "+f"(d[3])
        : "r"(a[0]), "r"(a[1]), "r"(a[2]), "r"(a[3]), "r"(b0), "r"(b1));
}

// grid-wide barrier: all GRID CTAs resident by construction
__device__ __forceinline__ void gbar(unsigned& gen) {
    __syncthreads();
    if (threadIdx.x == 0) {
        unsigned prev;
        asm volatile("atom.release.gpu.add.u32 %0, [%1], %2;"
                     : "=r"(prev) : "l"(&g_cnt), "r"(1u) : "memory");
        if (prev == GRID - 1) {
            asm volatile("st.relaxed.gpu.u32 [%0], %1;" :: "l"(&g_cnt), "r"(0u) : "memory");
            asm volatile("red.release.gpu.add.u32 [%0], %1;" :: "l"(&g_gen), "r"(1u) : "memory");
        } else {
            unsigned v;
            while (true) {
                asm volatile("ld.acquire.gpu.u32 %0, [%1];" : "=r"(v) : "l"(&g_gen) : "memory");
                if (v != gen) break;
                asm volatile("nanosleep.u32 32;");
            }
        }
    }
    gen += 1;
    __syncthreads();
}

// ---------------------------------------------------------------------------
// One persistent kernel: init + 10 fused GEMM/Euler steps + finalize.
// ---------------------------------------------------------------------------
__global__ __launch_bounds__(THREADS, 1) void kuramoto_kernel(
    const float* __restrict__ theta_init,
    const float* __restrict__ Kmat,
    const float* __restrict__ omega,
    const float* __restrict__ Kg,
    float* __restrict__ out)
{
    extern __shared__ char smem[];
    const uint32_t sAu = smem_u32(smem);
    const uint32_t sBu = sAu + SA_BYTES;

    const int t = threadIdx.x;
    const int lane = t & 31;
    const int wid = t >> 5;
    const int wm = wid & 3;
    const int wn = wid >> 2;
    const int it = blockIdx.x & 15;          // i-tile
    const int nt = blockIdx.x >> 4;          // n-tile (0..7)
    const int i0 = it * TM;
    const int n0 = nt * TN;

    unsigned gen;
    asm volatile("ld.acquire.gpu.u32 %0, [%1];" : "=r"(gen) : "l"(&g_gen) : "memory");

    // ---------------- init: zero reducers --------------------------------
    if (blockIdx.x == 0 && t < BB) { g_redS[t] = 0.f; g_redC[t] = 0.f; }

    // ---------------- init: A tile f32 -> bf16, swizzled, resident -------
    #pragma unroll 4
    for (int u = t; u < NCH * TM * 8; u += THREADS) {    // 8192 16B units
        int k = u >> 9;
        int rem = u & 511;
        int r = rem >> 3;
        int c = rem & 7;
        const float* src = Kmat + (size_t)(i0 + r) * NN + k * BK + c * 8;
        float4 v0 = *reinterpret_cast<const float4*>(src);
        float4 v1 = *reinterpret_cast<const float4*>(src + 4);
        union { uint4 q; __nv_bfloat162 h[4]; } w;
        w.h[0] = __floats2bfloat162_rn(v0.x, v0.y);
        w.h[1] = __floats2bfloat162_rn(v0.z, v0.w);
        w.h[2] = __floats2bfloat162_rn(v1.x, v1.y);
        w.h[3] = __floats2bfloat162_rn(v1.z, v1.w);
        *reinterpret_cast<uint4*>(smem + k * 8192 + r * 128 + ((c ^ (r & 7)) << 4)) = w.q;
    }

    // ---------------- init: per-thread state registers --------------------
    const int tq = lane >> 2, tr = lane & 3;
    const int sub = lane >> 3, lr = lane & 7;
    float th[2][2], sr[2][2], cr[2][2];      // [nb][half]
    float om[2];
    int ig[2], bg[2];
    #pragma unroll
    for (int half = 0; half < 2; half++) {
        ig[half] = i0 + wm * 16 + half * 8 + tq;
        om[half] = omega[ig[half]];
    }
    #pragma unroll
    for (int nb = 0; nb < 2; nb++) bg[nb] = nt * 16 + wn * 8 + nb * 4 + tr;

    const float kgn = Kg[0] * (1.0f / (float)NN);

    #pragma unroll
    for (int nb = 0; nb < 2; nb++)
        #pragma unroll
        for (int half = 0; half < 2; half++) {
            float tv = theta_init[bg[nb] * NN + ig[half]];
            th[nb][half] = tv;
            float s, c;
            sincosf(tv, &s, &c);
            sr[nb][half] = s;
            cr[nb][half] = c;
            g_scB[0][(size_t)(2 * bg[nb]) * NN + ig[half]]     = __float2bfloat16(s);
            g_scB[0][(size_t)(2 * bg[nb] + 1) * NN + ig[half]] = __float2bfloat16(c);
        }

    gbar(gen);

    // ---------------- precomputed addressing ------------------------------
    const int arow = wm * 16 + ((sub & 1) << 3) + lr;
    const int acsel = sub >> 1;
    const int axor = arow & 7;
    const uint32_t aBase = sAu + (uint32_t)(arow * 128);

    const int brow = wn * 16 + ((sub >> 1) << 3) + lr;
    const int bcsel = sub & 1;
    const int bxor = brow & 7;
    const uint32_t bRowOff = (uint32_t)(brow * 128);

    const uint32_t bdstoff = (uint32_t)((t >> 3) * 128 + (((t & 7) ^ ((t >> 3) & 7)) << 4));
    const size_t bsrcoff = (size_t)(n0 + (t >> 3)) * NN + (t & 7) * 8;

    // ---------------- 10 fused steps --------------------------------------
    for (int s = 0; s < STEPS; s++) {
        const __nv_bfloat16* __restrict__ bsrc_t = g_scB[s & 1] + bsrcoff;
        __nv_bfloat16* __restrict__ Bdst = g_scB[(s + 1) & 1];

        float acc0[4] = {0.f, 0.f, 0.f, 0.f};
        float acc1[4] = {0.f, 0.f, 0.f, 0.f};

        // prologue: 3 chunks in flight
        cp16(sBu + 0 * SB_STAGE + bdstoff, bsrc_t + 0 * BK); CP_COMMIT();
        cp16(sBu + 1 * SB_STAGE + bdstoff, bsrc_t + 1 * BK); CP_COMMIT();
        cp16(sBu + 2 * SB_STAGE + bdstoff, bsrc_t + 2 * BK); CP_COMMIT();

        for (int k = 0; k < NCH; k++) {
            CP_WAIT2();                     // chunk k ready (empty groups pad the tail)
            __syncthreads();                // all threads' copies + buf(k-1) consumers done
            if (k + 3 < NCH)
                cp16(sBu + ((k + 3) & 3) * SB_STAGE + bdstoff, bsrc_t + (k + 3) * BK);
            CP_COMMIT();

            const uint32_t aBk = aBase + (uint32_t)(k * 8192);
            const uint32_t bBk = sBu + (uint32_t)((k & 3) * SB_STAGE) + bRowOff;
            #pragma unroll
            for (int ks = 0; ks < 4; ks++) {
                uint32_t a[4], b[4];
                ldm4(a[0], a[1], a[2], a[3], aBk + (uint32_t)((((ks * 2 + acsel) ^ axor)) << 4));
                ldm4(b[0], b[1], b[2], b[3], bBk + (uint32_t)((((ks * 2 + bcsel) ^ bxor)) << 4));
                mma_bf16(acc0, a, b[0], b[1]);
                mma_bf16(acc1, a, b[2], b[3]);
            }
        }

        // fused Euler epilogue (state in registers; no per-step wrap needed)
        #pragma unroll
        for (int nb = 0; nb < 2; nb++) {
            const float* acc = nb ? acc1 : acc0;
            #pragma unroll
            for (int half = 0; half < 2; half++) {
                float S = acc[half * 2 + 0];
                float C = acc[half * 2 + 1];
                float coup = cr[nb][half] * S - sr[nb][half] * C;
                float tn = th[nb][half] + DT * (om[half] + kgn * coup);
                th[nb][half] = tn;
                float sv, cv;
                sincosf(tn, &sv, &cv);
                sr[nb][half] = sv;
                cr[nb][half] = cv;
                Bdst[(size_t)(2 * bg[nb]) * NN + ig[half]]     = __float2bfloat16(sv);
                Bdst[(size_t)(2 * bg[nb] + 1) * NN + ig[half]] = __float2bfloat16(cv);
            }
        }
        if (s != STEPS - 1) gbar(gen);
    }

    // ---------------- finalize ---------------------------------------------
    float* redS = reinterpret_cast<float*>(smem + SA_BYTES + SB_BYTES);
    float* redC = redS + 16;
    __syncthreads();                        // sB no longer read; safe to reuse region
    if (t < 16) { redS[t] = 0.f; redC[t] = 0.f; }
    __syncthreads();

    #pragma unroll
    for (int nb = 0; nb < 2; nb++) {
        float ssum = sr[nb][0] + sr[nb][1];
        float csum = cr[nb][0] + cr[nb][1];
        int bl = wn * 8 + nb * 4 + tr;
        atomicAdd(&redS[bl], ssum);
        atomicAdd(&redC[bl], csum);
        #pragma unroll
        for (int half = 0; half < 2; half++)
            out[(size_t)bg[nb] * NN + ig[half]] = atan2f(sr[nb][half], cr[nb][half]);
    }
    __syncthreads();
    if (t < 16) {
        atomicAdd(&g_redS[nt * 16 + t], redS[t]);
        atomicAdd(&g_redC[nt * 16 + t], redC[t]);
    }
    gbar(gen);

    if (t == 0) {
        int b = blockIdx.x;                 // 128 CTAs == BB batches
        float sm = g_redS[b] * (1.0f / (float)NN);
        float cm = g_redC[b] * (1.0f / (float)NN);
        out[(size_t)BB * NN + b] = sqrtf(cm * cm + sm * sm);
    }
}

// ---------------------------------------------------------------------------
extern "C" void kernel_launch(void* const* d_in, const int* in_sizes, int n_in,
                              void* d_out, int out_size) {
    const float* theta_init = (const float*)d_in[0];
    const float* Kmat       = (const float*)d_in[1];
    const float* omega      = (const float*)d_in[2];
    const float* Kg         = (const float*)d_in[3];
    float* out = (float*)d_out;

    cudaFuncSetAttribute(kuramoto_kernel,
                         cudaFuncAttributeMaxDynamicSharedMemorySize, SM_TOTAL);
    kuramoto_kernel<<<GRID, THREADS, SM_TOTAL>>>(theta_init, Kmat, omega, Kg, out);
}

// round 9
// speedup vs baseline: 1.7513x; 1.0078x over previous
#include <cuda_runtime.h>
#include <cuda_bf16.h>
#include <math.h>
#include <stdint.h>

#define NN 1024
#define BB 128
#define NT 256
#define DT 0.1f
#define STEPS 10

#define TM 64
#define TN 32
#define BK 64
#define NCH 16            // K chunks of 64
#define GRID 128          // 16 i-tiles x 8 n-tiles, all co-resident (<=148 SMs)
#define THREADS 256

#define SA_BYTES (NCH * TM * BK * 2)   /* 128 KB: whole A tile, resident */
#define SB_STAGE (TN * BK * 2)         /* 4 KB per pipeline stage */
#define SB_BYTES (4 * SB_STAGE)        /* 4 stages */
#define SM_TOTAL (SA_BYTES + SB_BYTES + 512)

// ---------------- device scratch (no cudaMalloc) ----------------------------
__device__ __nv_bfloat16 g_scB[2][NT * NN];   // ping-pong B operand [n][j]
__device__ float g_redS[BB];
__device__ float g_redC[BB];
__device__ unsigned g_cnt = 0;
__device__ unsigned g_gen = 0;

// ---------------- PTX helpers ----------------------------------------------
__device__ __forceinline__ uint32_t smem_u32(const void* p) {
    uint32_t a;
    asm("{ .reg .u64 t; cvta.to.shared.u64 t, %1; cvt.u32.u64 %0, t; }" : "=r"(a) : "l"(p));
    return a;
}
__device__ __forceinline__ void cp16(uint32_t dst, const void* src) {
    asm volatile("cp.async.cg.shared.global [%0], [%1], 16;" :: "r"(dst), "l"(src));
}
#define CP_COMMIT() asm volatile("cp.async.commit_group;" ::: "memory")
#define CP_WAIT2()  asm volatile("cp.async.wait_group 2;" ::: "memory")

__device__ __forceinline__ void ldm4(uint32_t& r0, uint32_t& r1, uint32_t& r2, uint32_t& r3,
                                     uint32_t addr) {
    asm volatile("ldmatrix.sync.aligned.m8n8.x4.shared.b16 {%0,%1,%2,%3}, [%4];"
                 : "=r"(r0), "=r"(r1), "=r"(r2), "=r"(r3) : "r"(addr));
}
__device__ __forceinline__ void mma_bf16(float* d, const uint32_t* a, uint32_t b0, uint32_t b1) {
    asm volatile(
        "mma.sync.aligned.m16n8k16.row.col.f32.bf16.bf16.f32 "
        "{%0,%1,%2,%3}, {%4,%5,%6,%7}, {%8,%9}, {%0,%1,%2,%3};"
        : "+f"(d[0]), "+f"(d[1]), "+f"(d[2]), "+f"(d[3])
        : "r"(a[0]), "r"(a[1]), "r"(a[2]), "r"(a[3]), "r"(b0), "r"(b1));
}

// grid-wide barrier: all GRID CTAs resident by construction
__device__ __forceinline__ void gbar(unsigned& gen) {
    __syncthreads();
    if (threadIdx.x == 0) {
        unsigned prev;
        asm volatile("atom.release.gpu.add.u32 %0, [%1], %2;"
                     : "=r"(prev) : "l"(&g_cnt), "r"(1u) : "memory");
        if (prev == GRID - 1) {
            asm volatile("st.relaxed.gpu.u32 [%0], %1;" :: "l"(&g_cnt), "r"(0u) : "memory");
            asm volatile("red.release.gpu.add.u32 [%0], %1;" :: "l"(&g_gen), "r"(1u) : "memory");
        } else {
            unsigned v;
            while (true) {
                asm volatile("ld.acquire.gpu.u32 %0, [%1];" : "=r"(v) : "l"(&g_gen) : "memory");
                if (v != gen) break;
                asm volatile("nanosleep.u32 32;");
            }
        }
    }
    gen += 1;
    __syncthreads();
}

// ---------------------------------------------------------------------------
// One persistent kernel: init + 10 fused GEMM/Euler steps + finalize.
// ---------------------------------------------------------------------------
__global__ __launch_bounds__(THREADS, 1) void kuramoto_kernel(
    const float* __restrict__ theta_init,
    const float* __restrict__ Kmat,
    const float* __restrict__ omega,
    const float* __restrict__ Kg,
    float* __restrict__ out)
{
    extern __shared__ char smem[];
    const uint32_t sAu = smem_u32(smem);
    const uint32_t sBu = sAu + SA_BYTES;

    const int t = threadIdx.x;
    const int lane = t & 31;
    const int wid = t >> 5;
    const int wm = wid & 3;
    const int wn = wid >> 2;
    const int it = blockIdx.x & 15;          // i-tile
    const int nt = blockIdx.x >> 4;          // n-tile (0..7)
    const int i0 = it * TM;
    const int n0 = nt * TN;

    unsigned gen;
    asm volatile("ld.acquire.gpu.u32 %0, [%1];" : "=r"(gen) : "l"(&g_gen) : "memory");

    // ---------------- init: zero reducers --------------------------------
    if (blockIdx.x == 0 && t < BB) { g_redS[t] = 0.f; g_redC[t] = 0.f; }

    // ---------------- init: A tile f32 -> bf16, swizzled, resident -------
    #pragma unroll 4
    for (int u = t; u < NCH * TM * 8; u += THREADS) {    // 8192 16B units
        int k = u >> 9;
        int rem = u & 511;
        int r = rem >> 3;
        int c = rem & 7;
        const float* src = Kmat + (size_t)(i0 + r) * NN + k * BK + c * 8;
        float4 v0 = *reinterpret_cast<const float4*>(src);
        float4 v1 = *reinterpret_cast<const float4*>(src + 4);
        union { uint4 q; __nv_bfloat162 h[4]; } w;
        w.h[0] = __floats2bfloat162_rn(v0.x, v0.y);
        w.h[1] = __floats2bfloat162_rn(v0.z, v0.w);
        w.h[2] = __floats2bfloat162_rn(v1.x, v1.y);
        w.h[3] = __floats2bfloat162_rn(v1.z, v1.w);
        *reinterpret_cast<uint4*>(smem + k * 8192 + r * 128 + ((c ^ (r & 7)) << 4)) = w.q;
    }

    // ---------------- init: per-thread state registers --------------------
    const int tq = lane >> 2, tr = lane & 3;
    const int sub = lane >> 3, lr = lane & 7;
    float th[2][2], sr[2][2], cr[2][2];      // [nb][half]
    float om[2];
    int ig[2], bg[2];
    #pragma unroll
    for (int half = 0; half < 2; half++) {
        ig[half] = i0 + wm * 16 + half * 8 + tq;
        om[half] = omega[ig[half]];
    }
    #pragma unroll
    for (int nb = 0; nb < 2; nb++) bg[nb] = nt * 16 + wn * 8 + nb * 4 + tr;

    const float kgn = Kg[0] * (1.0f / (float)NN);

    #pragma unroll
    for (int nb = 0; nb < 2; nb++)
        #pragma unroll
        for (int half = 0; half < 2; half++) {
            float tv = theta_init[bg[nb] * NN + ig[half]];
            th[nb][half] = tv;
            float s, c;
            sincosf(tv, &s, &c);
            sr[nb][half] = s;
            cr[nb][half] = c;
            g_scB[0][(size_t)(2 * bg[nb]) * NN + ig[half]]     = __float2bfloat16(s);
            g_scB[0][(size_t)(2 * bg[nb] + 1) * NN + ig[half]] = __float2bfloat16(c);
        }

    gbar(gen);

    // ---------------- precomputed addressing ------------------------------
    const int arow = wm * 16 + ((sub & 1) << 3) + lr;
    const int acsel = sub >> 1;
    const int axor = arow & 7;
    const uint32_t aBase = sAu + (uint32_t)(arow * 128);

    const int brow = wn * 16 + ((sub >> 1) << 3) + lr;
    const int bcsel = sub & 1;
    const int bxor = brow & 7;
    const uint32_t bRowOff = (uint32_t)(brow * 128);

    const uint32_t bdstoff = (uint32_t)((t >> 3) * 128 + (((t & 7) ^ ((t >> 3) & 7)) << 4));
    const size_t bsrcoff = (size_t)(n0 + (t >> 3)) * NN + (t & 7) * 8;

    // ---------------- 10 fused steps --------------------------------------
    for (int s = 0; s < STEPS; s++) {
        const __nv_bfloat16* __restrict__ bsrc_t = g_scB[s & 1] + bsrcoff;
        __nv_bfloat16* __restrict__ Bdst = g_scB[(s + 1) & 1];

        float acc0[4] = {0.f, 0.f, 0.f, 0.f};
        float acc1[4] = {0.f, 0.f, 0.f, 0.f};

        // prologue: 3 chunks in flight
        cp16(sBu + 0 * SB_STAGE + bdstoff, bsrc_t + 0 * BK); CP_COMMIT();
        cp16(sBu + 1 * SB_STAGE + bdstoff, bsrc_t + 1 * BK); CP_COMMIT();
        cp16(sBu + 2 * SB_STAGE + bdstoff, bsrc_t + 2 * BK); CP_COMMIT();

        for (int k = 0; k < NCH; k++) {
            CP_WAIT2();                     // chunk k ready (empty groups pad the tail)
            __syncthreads();                // all threads' copies + buf(k-1) consumers done
            if (k + 3 < NCH)
                cp16(sBu + ((k + 3) & 3) * SB_STAGE + bdstoff, bsrc_t + (k + 3) * BK);
            CP_COMMIT();

            const uint32_t aBk = aBase + (uint32_t)(k * 8192);
            const uint32_t bBk = sBu + (uint32_t)((k & 3) * SB_STAGE) + bRowOff;
            #pragma unroll
            for (int ks = 0; ks < 4; ks++) {
                uint32_t a[4], b[4];
                ldm4(a[0], a[1], a[2], a[3], aBk + (uint32_t)((((ks * 2 + acsel) ^ axor)) << 4));
                ldm4(b[0], b[1], b[2], b[3], bBk + (uint32_t)((((ks * 2 + bcsel) ^ bxor)) << 4));
                mma_bf16(acc0, a, b[0], b[1]);
                mma_bf16(acc1, a, b[2], b[3]);
            }
        }

        // fused Euler epilogue (state in registers; no per-step wrap needed)
        #pragma unroll
        for (int nb = 0; nb < 2; nb++) {
            const float* acc = nb ? acc1 : acc0;
            #pragma unroll
            for (int half = 0; half < 2; half++) {
                float S = acc[half * 2 + 0];
                float C = acc[half * 2 + 1];
                float coup = cr[nb][half] * S - sr[nb][half] * C;
                float tn = th[nb][half] + DT * (om[half] + kgn * coup);
                th[nb][half] = tn;
                float sv, cv;
                sincosf(tn, &sv, &cv);
                sr[nb][half] = sv;
                cr[nb][half] = cv;
                Bdst[(size_t)(2 * bg[nb]) * NN + ig[half]]     = __float2bfloat16(sv);
                Bdst[(size_t)(2 * bg[nb] + 1) * NN + ig[half]] = __float2bfloat16(cv);
            }
        }
        if (s != STEPS - 1) gbar(gen);
    }

    // ---------------- finalize ---------------------------------------------
    float* redS = reinterpret_cast<float*>(smem + SA_BYTES + SB_BYTES);
    float* redC = redS + 16;
    __syncthreads();                        // sB no longer read; safe to reuse region
    if (t < 16) { redS[t] = 0.f; redC[t] = 0.f; }
    __syncthreads();

    #pragma unroll
    for (int nb = 0; nb < 2; nb++) {
        float ssum = sr[nb][0] + sr[nb][1];
        float csum = cr[nb][0] + cr[nb][1];
        int bl = wn * 8 + nb * 4 + tr;
        atomicAdd(&redS[bl], ssum);
        atomicAdd(&redC[bl], csum);
        #pragma unroll
        for (int half = 0; half < 2; half++)
            out[(size_t)bg[nb] * NN + ig[half]] = atan2f(sr[nb][half], cr[nb][half]);
    }
    __syncthreads();
    if (t < 16) {
        atomicAdd(&g_redS[nt * 16 + t], redS[t]);
        atomicAdd(&g_redC[nt * 16 + t], redC[t]);
    }
    gbar(gen);

    if (t == 0) {
        int b = blockIdx.x;                 // 128 CTAs == BB batches
        float sm = g_redS[b] * (1.0f / (float)NN);
        float cm = g_redC[b] * (1.0f / (float)NN);
        out[(size_t)BB * NN + b] = sqrtf(cm * cm + sm * sm);
    }
}

// ---------------------------------------------------------------------------
extern "C" void kernel_launch(void* const* d_in, const int* in_sizes, int n_in,
                              void* d_out, int out_size) {
    const float* theta_init = (const float*)d_in[0];
    const float* Kmat       = (const float*)d_in[1];
    const float* omega      = (const float*)d_in[2];
    const float* Kg         = (const float*)d_in[3];
    float* out = (float*)d_out;

    cudaFuncSetAttribute(kuramoto_kernel,
                         cudaFuncAttributeMaxDynamicSharedMemorySize, SM_TOTAL);
    kuramoto_kernel<<<GRID, THREADS, SM_TOTAL>>>(theta_init, Kmat, omega, Kg, out);
}